// round 1
// baseline (speedup 1.0000x reference)
#include <cuda_runtime.h>
#include <cuda_bf16.h>

// EdgeNetwork: out = tanh(relu(cat(h[dst], h[src], dR) @ W1 + b1) @ W2 + b2)
// E=640000, F=128, K1=257, MID=192, OUT=128. All fp32.
//
// Round-0 baseline: fp32 SIMT tiled GEMM, 64 edges per block, 256 threads,
// packed fma.rn.f32x2 accumulators (sm_103a FFMA2, PTX-only pattern).

#define E_TOTAL 640000
#define FDIM    128
#define K1      257
#define MID     192
#define OUTD    128
#define TILE_E  64
#define LDI     260   // padded pitch of input tile (257 -> 260, 16B aligned rows)
#define LDH     196   // padded pitch of hidden tile
#define NTHREADS 256

// smem float offsets
#define S_INP   0                    // [64][260] = 16640
#define S_W     16640                // staging: max(16*192, 16*128) = 3072
#define S_HID   19712                // [64][196] = 12544
#define SMEM_FLOATS 32256            // = 129024 bytes

// ---- packed f32x2 helpers ----
__device__ __forceinline__ unsigned long long pk2(float lo, float hi) {
    unsigned long long r;
    asm("mov.b64 %0, {%1, %2};" : "=l"(r) : "f"(lo), "f"(hi));
    return r;
}
__device__ __forceinline__ void upk2(unsigned long long v, float& lo, float& hi) {
    asm("mov.b64 {%0, %1}, %2;" : "=f"(lo), "=f"(hi) : "l"(v));
}
__device__ __forceinline__ void fma2(unsigned long long& d,
                                     unsigned long long a,
                                     unsigned long long b) {
    asm("fma.rn.f32x2 %0, %1, %2, %0;" : "+l"(d) : "l"(a), "l"(b));
}

__global__ void __launch_bounds__(NTHREADS, 1)
edge_mlp_kernel(const float* __restrict__ h,
                const float* __restrict__ dR,
                const int*   __restrict__ src_idx,
                const int*   __restrict__ dst_idx,
                const float* __restrict__ W1,
                const float* __restrict__ b1,
                const float* __restrict__ W2,
                const float* __restrict__ b2,
                float*       __restrict__ out)
{
    extern __shared__ float smem[];
    float* s_inp = smem + S_INP;
    float* s_w   = smem + S_W;
    float* s_hid = smem + S_HID;

    const int tid = threadIdx.x;
    const int tx  = tid & 15;        // column group 0..15
    const int ty  = tid >> 4;        // row group 0..15 (4 rows each)
    const int ty4 = ty * 4;
    const int e0  = blockIdx.x * TILE_E;

    // ---------------- Gather phase: build inp tile [64][257] -----------------
    // Row layout: cols [0,128) = h[dst], [128,256) = h[src], col 256 = dR.
    {
        const float4* h4 = reinterpret_cast<const float4*>(h);
        #pragma unroll
        for (int idx = tid; idx < TILE_E * 64; idx += NTHREADS) {
            int row = idx >> 6;           // edge within tile
            int q   = idx & 63;           // float4 slot: 0..31 dst, 32..63 src
            int e   = e0 + row;
            float4 v;
            if (q < 32) v = h4[dst_idx[e] * 32 + q];
            else        v = h4[src_idx[e] * 32 + (q - 32)];
            // dst part -> cols q*4 (0..124); src part -> 128+(q-32)*4 = q*4. Same!
            *reinterpret_cast<float4*>(&s_inp[row * LDI + q * 4]) = v;
        }
        if (tid < TILE_E) s_inp[tid * LDI + 256] = dR[e0 + tid];
    }
    __syncthreads();

    // ---------------- GEMM1: hid[64][192] = relu(inp @ W1 + b1) --------------
    // Per thread: 4 rows (ty4..ty4+3) x 12 cols (tx + 16c), packed as 6 f32x2.
    unsigned long long acc1[4][6];
    #pragma unroll
    for (int i = 0; i < 4; ++i)
        #pragma unroll
        for (int c = 0; c < 6; ++c) acc1[i][c] = 0ull;

    for (int t = 0; t < 16; ++t) {       // k tiles of 16 over k=0..255
        const int k0 = t * 16;
        __syncthreads();                 // protect s_w from previous tile's readers
        #pragma unroll
        for (int j = tid; j < 16 * MID; j += NTHREADS)
            s_w[j] = W1[k0 * MID + j];   // contiguous, coalesced
        __syncthreads();

        #pragma unroll
        for (int kk = 0; kk < 16; ++kk) {
            const float* wrow = &s_w[kk * MID + tx];
            unsigned long long pb[6];
            #pragma unroll
            for (int c = 0; c < 6; ++c)
                pb[c] = pk2(wrow[32 * c], wrow[32 * c + 16]);

            const int k = k0 + kk;
            #pragma unroll
            for (int i = 0; i < 4; ++i) {
                float a = s_inp[(ty4 + i) * LDI + k];
                unsigned long long pa = pk2(a, a);
                #pragma unroll
                for (int c = 0; c < 6; ++c) fma2(acc1[i][c], pa, pb[c]);
            }
        }
    }

    // Epilogue GEMM1: fold k=256 (dR column), bias, relu -> s_hid
    {
        float wl[12], bi[12];
        #pragma unroll
        for (int c = 0; c < 12; ++c) {
            wl[c] = W1[256 * MID + tx + 16 * c];
            bi[c] = b1[tx + 16 * c];
        }
        #pragma unroll
        for (int i = 0; i < 4; ++i) {
            const int row = ty4 + i;
            const float ar = s_inp[row * LDI + 256];
            #pragma unroll
            for (int c = 0; c < 6; ++c) {
                float lo, hi;
                upk2(acc1[i][c], lo, hi);
                float v0 = fmaf(ar, wl[2 * c],     lo) + bi[2 * c];
                float v1 = fmaf(ar, wl[2 * c + 1], hi) + bi[2 * c + 1];
                v0 = fmaxf(v0, 0.0f);
                v1 = fmaxf(v1, 0.0f);
                s_hid[row * LDH + tx + 32 * c]      = v0;
                s_hid[row * LDH + tx + 32 * c + 16] = v1;
            }
        }
    }
    // visibility of s_hid + s_w reuse handled by sync at top of next loop

    // ---------------- GEMM2: out[64][128] = tanh(hid @ W2 + b2) --------------
    unsigned long long acc2[4][4];
    #pragma unroll
    for (int i = 0; i < 4; ++i)
        #pragma unroll
        for (int c = 0; c < 4; ++c) acc2[i][c] = 0ull;

    for (int t = 0; t < 12; ++t) {       // k tiles of 16 over k=0..191
        const int k0 = t * 16;
        __syncthreads();
        #pragma unroll
        for (int j = tid; j < 16 * OUTD; j += NTHREADS)
            s_w[j] = W2[k0 * OUTD + j];
        __syncthreads();

        #pragma unroll
        for (int kk = 0; kk < 16; ++kk) {
            const float* wrow = &s_w[kk * OUTD + tx];
            unsigned long long pb[4];
            #pragma unroll
            for (int c = 0; c < 4; ++c)
                pb[c] = pk2(wrow[32 * c], wrow[32 * c + 16]);

            const int k = k0 + kk;
            #pragma unroll
            for (int i = 0; i < 4; ++i) {
                float a = s_hid[(ty4 + i) * LDH + k];
                unsigned long long pa = pk2(a, a);
                #pragma unroll
                for (int c = 0; c < 4; ++c) fma2(acc2[i][c], pa, pb[c]);
            }
        }
    }

    // Epilogue GEMM2: bias + tanh -> global
    {
        float bi[8];
        #pragma unroll
        for (int c = 0; c < 8; ++c) bi[c] = b2[tx + 16 * c];
        #pragma unroll
        for (int i = 0; i < 4; ++i) {
            const int e = e0 + ty4 + i;
            float* orow = out + (long long)e * OUTD;
            #pragma unroll
            for (int c = 0; c < 4; ++c) {
                float lo, hi;
                upk2(acc2[i][c], lo, hi);
                orow[tx + 32 * c]      = tanhf(lo + bi[2 * c]);
                orow[tx + 32 * c + 16] = tanhf(hi + bi[2 * c + 1]);
            }
        }
    }
}

extern "C" void kernel_launch(void* const* d_in, const int* in_sizes, int n_in,
                              void* d_out, int out_size) {
    const float* h   = (const float*)d_in[0];
    const float* dR  = (const float*)d_in[1];
    const int*   src = (const int*)  d_in[2];
    const int*   dst = (const int*)  d_in[3];
    const float* W1  = (const float*)d_in[4];
    const float* b1  = (const float*)d_in[5];
    const float* W2  = (const float*)d_in[6];
    const float* b2  = (const float*)d_in[7];
    float* out = (float*)d_out;

    const int smem_bytes = SMEM_FLOATS * (int)sizeof(float);  // 129024
    cudaFuncSetAttribute(edge_mlp_kernel,
                         cudaFuncAttributeMaxDynamicSharedMemorySize, smem_bytes);

    const int nblocks = E_TOTAL / TILE_E;   // 10000
    edge_mlp_kernel<<<nblocks, NTHREADS, smem_bytes>>>(
        h, dR, src, dst, W1, b1, W2, b2, out);
}